// round 3
// baseline (speedup 1.0000x reference)
#include <cuda_runtime.h>
#include <math.h>

#define BATCH 8
#define SEQ   2048
#define DIM   128

// attention tiling
#define BM 32
#define BN 32
#define NQT (SEQ / BM)           // 64
#define NITEMS (NQT * BATCH)     // 512
#define ATHREADS 128

// qkv tiling
#define QBM 64

// Scratch (device globals — no allocation allowed)
__device__ float g_q[BATCH * SEQ * DIM];        // [b][t][d]
__device__ float g_k[BATCH * SEQ * DIM];        // [b][t][d]
__device__ float g_vt[BATCH * DIM * SEQ];       // [b][d][t]  (transposed V)

typedef unsigned long long u64;

__device__ __forceinline__ void ffma2(u64& d, u64 a, u64 b) {
    asm("fma.rn.f32x2 %0, %1, %2, %3;" : "=l"(d) : "l"(a), "l"(b), "l"(d));
}
__device__ __forceinline__ u64 fmul2(u64 a, u64 b) {
    u64 r; asm("mul.rn.f32x2 %0, %1, %2;" : "=l"(r) : "l"(a), "l"(b)); return r;
}
__device__ __forceinline__ u64 pack2(float x) {
    u64 r; asm("mov.b64 %0, {%1, %1};" : "=l"(r) : "f"(x)); return r;
}
__device__ __forceinline__ float lo_plus_hi(u64 v) {
    float2 f = *reinterpret_cast<float2*>(&v);
    return f.x + f.y;
}
__device__ __forceinline__ float rmax16(float v) {
    v = fmaxf(v, __shfl_xor_sync(0xffffffffu, v, 1));
    v = fmaxf(v, __shfl_xor_sync(0xffffffffu, v, 2));
    v = fmaxf(v, __shfl_xor_sync(0xffffffffu, v, 4));
    v = fmaxf(v, __shfl_xor_sync(0xffffffffu, v, 8));
    return v;
}
__device__ __forceinline__ float rsum16(float v) {
    v += __shfl_xor_sync(0xffffffffu, v, 1);
    v += __shfl_xor_sync(0xffffffffu, v, 2);
    v += __shfl_xor_sync(0xffffffffu, v, 4);
    v += __shfl_xor_sync(0xffffffffu, v, 8);
    return v;
}
// store a float4 to an 8B-aligned (possibly not 16B-aligned) smem row
__device__ __forceinline__ void st4_as_2x2(float* p, float4 v) {
    *(float2*)(p)     = make_float2(v.x, v.y);
    *(float2*)(p + 2) = make_float2(v.z, v.w);
}

// ---------------------------------------------------------------------------
// QKV projection: y[b,t,d] = sum_c x[b,t,c] * W[d,c]
// grid (SEQ/QBM, BATCH, 3), block 256.
// which==0 -> g_q natural, which==1 -> g_k natural, which==2 -> g_vt transposed
// ---------------------------------------------------------------------------
__global__ __launch_bounds__(256, 1)
void qkv_kernel(const float* __restrict__ x,
                const float* __restrict__ Wk,
                const float* __restrict__ Wq,
                const float* __restrict__ Wv) {
    extern __shared__ float sm[];
    float* sWt = sm;               // [DIM][DIM] : sWt[c*DIM + d]
    float* sX  = sm + DIM * DIM;   // [QBM][DIM]

    const int tq    = blockIdx.x;
    const int b     = blockIdx.y;
    const int which = blockIdx.z;
    const float* W  = (which == 0) ? Wq : (which == 1) ? Wk : Wv;
    const int tid = threadIdx.x;

    // Load W transposed into SMEM
    {
        int d  = tid >> 1;
        int c0 = (tid & 1) * 64;
        const float4* src = (const float4*)(W + d * DIM + c0);
        #pragma unroll
        for (int i = 0; i < 16; i++) {
            float4 w = src[i];
            int c = c0 + i * 4;
            sWt[(c + 0) * DIM + d] = w.x;
            sWt[(c + 1) * DIM + d] = w.y;
            sWt[(c + 2) * DIM + d] = w.z;
            sWt[(c + 3) * DIM + d] = w.w;
        }
    }
    // Load x tile [64][128]  (stride 128 -> float4 OK)
    {
        const float4* src = (const float4*)(x + ((size_t)b * SEQ + tq * QBM) * DIM);
        float4* dst = (float4*)sX;
        #pragma unroll
        for (int i = 0; i < 8; i++)
            dst[tid + i * 256] = src[tid + i * 256];
    }
    __syncthreads();

    const int cx = tid & 31;   // 4 output cols d = 4*cx..
    const int ry = tid >> 5;   // 8 output rows r = ry*8..
    float acc[8][4];
    #pragma unroll
    for (int i = 0; i < 8; i++)
        #pragma unroll
        for (int j = 0; j < 4; j++) acc[i][j] = 0.f;

    #pragma unroll 4
    for (int c = 0; c < DIM; c++) {
        float4 w = *(const float4*)(sWt + c * DIM + cx * 4);
        #pragma unroll
        for (int i = 0; i < 8; i++) {
            float xv = sX[(ry * 8 + i) * DIM + c];
            acc[i][0] += xv * w.x;
            acc[i][1] += xv * w.y;
            acc[i][2] += xv * w.z;
            acc[i][3] += xv * w.w;
        }
    }

    if (which != 2) {
        float* out = (which == 0) ? g_q : g_k;
        float* obase = out + ((size_t)b * SEQ + tq * QBM) * DIM;
        #pragma unroll
        for (int i = 0; i < 8; i++) {
            float4 o = make_float4(acc[i][0], acc[i][1], acc[i][2], acc[i][3]);
            *(float4*)(obase + (ry * 8 + i) * DIM + cx * 4) = o;
        }
    } else {
        // Stage tile in smem, then write transposed (coalesced along t) to g_vt
        __syncthreads();              // everyone done reading sWt/sX
        float* sOut = sm;             // [QBM][130] (stride 130: use float2 stores)
        #pragma unroll
        for (int i = 0; i < 8; i++) {
            st4_as_2x2(sOut + (ry * 8 + i) * 130 + cx * 4,
                       make_float4(acc[i][0], acc[i][1], acc[i][2], acc[i][3]));
        }
        __syncthreads();
        int dr = tid >> 1;            // d row 0..127
        int t0 = (tid & 1) * 32;      // half of the 64 tokens
        float* gbase = g_vt + ((size_t)b * DIM + dr) * SEQ + tq * QBM + t0;
        #pragma unroll
        for (int k4 = 0; k4 < 8; k4++) {
            float4 o;
            o.x = sOut[(t0 + k4 * 4 + 0) * 130 + dr];
            o.y = sOut[(t0 + k4 * 4 + 1) * 130 + dr];
            o.z = sOut[(t0 + k4 * 4 + 2) * 130 + dr];
            o.w = sOut[(t0 + k4 * 4 + 3) * 130 + dr];
            *(float4*)(gbase + k4 * 4) = o;
        }
    }
}

// ---------------------------------------------------------------------------
// Flash attention, fp32, packed f32x2 math. 128 threads, BM=BN=32.
// 4 CTAs/SM. Snake work ordering for per-SM balance (placement = LUT[bid%148]).
// ---------------------------------------------------------------------------
__global__ __launch_bounds__(ATHREADS, 4)
void attn_kernel(float* __restrict__ out) {
    extern __shared__ float sm[];
    float* sQ  = sm;            // [32][130]
    float* sK  = sm + 4160;     // [32][130]
    float* sVt = sm + 8320;     // [128][34]
    float* sS  = sm + 12672;    // [32][32]
    float* sM  = sm + 13696;    // [32]
    float* sL  = sm + 13728;    // [32]
    float* sA  = sm + 13760;    // [32]

    const int tid = threadIdx.x;

    // snake ordering: co-resident bids are b, b+148, b+296, b+444
    const int s_ = blockIdx.x % 148;
    const int o_ = blockIdx.x / 148;
    const int idx = (o_ == 0) ? s_
                  : (o_ == 1) ? (295 - s_)
                  : (o_ == 2) ? (296 + s_)
                  :             (511 - s_);
    const int qt = (NQT - 1) - (idx >> 3);   // heavy first
    const int b  = idx & 7;
    const int qbase = qt * BM;

    const float scale = 0.08838834764831845f;   // 1/sqrt(128)

    // Load Q tile (pre-scaled): [32][128] -> sQ[32][130]
    {
        const float* Qg = g_q + ((size_t)b * SEQ + qbase) * DIM;
        #pragma unroll
        for (int k = 0; k < 8; k++) {
            int i4 = tid + k * 128;
            int r = i4 >> 5, dc = (i4 & 31) * 4;
            float4 v = *(const float4*)(Qg + r * DIM + dc);
            v.x *= scale; v.y *= scale; v.z *= scale; v.w *= scale;
            st4_as_2x2(sQ + r * 130 + dc, v);
        }
    }
    if (tid < BM) { sM[tid] = -1e30f; sL[tid] = 0.f; }

    const int txS = tid & 15;   // S cols: txS, txS+16
    const int tyS = tid >> 4;   // S rows: tyS*4 + i (i<4)
    const int cx  = tid & 31;   // O cols: cx + 32*j (j<4)
    const int ry  = tid >> 5;   // O rows: ry*8 + i (i<8)

    u64 acc2[8][4];
    #pragma unroll
    for (int i = 0; i < 8; i++)
        #pragma unroll
        for (int j = 0; j < 4; j++) acc2[i][j] = 0ull;

    const float* Kg = g_k  + (size_t)b * SEQ * DIM;
    const float* Vg = g_vt + (size_t)b * DIM * SEQ;

    for (int kt = 0; kt <= qt; kt++) {
        __syncthreads();   // previous PV done with sS/sVt; prev softmax done with sM

        // K tile [32][128] -> sK[32][130]
        #pragma unroll
        for (int k = 0; k < 8; k++) {
            int i4 = tid + k * 128;
            int r = i4 >> 5, dc = (i4 & 31) * 4;
            float4 v = *(const float4*)(Kg + ((size_t)(kt * BN + r)) * DIM + dc);
            st4_as_2x2(sK + r * 130 + dc, v);
        }
        // Vt tile [128][32] -> sVt[128][34]
        #pragma unroll
        for (int k = 0; k < 8; k++) {
            int i4 = tid + k * 128;
            int dr = i4 >> 3, cc = (i4 & 7) * 4;
            float4 v = *(const float4*)(Vg + (size_t)dr * SEQ + kt * BN + cc);
            st4_as_2x2(sVt + dr * 34 + cc, v);
        }
        __syncthreads();

        // S = Q @ K^T, packed along d (reduction). 4 rows x 2 cols per thread.
        u64 s2[4][2];
        #pragma unroll
        for (int i = 0; i < 4; i++) { s2[i][0] = 0ull; s2[i][1] = 0ull; }
        {
            const float* qb  = sQ + (tyS * 4) * 130;
            const float* kb0 = sK + txS * 130;
            const float* kb1 = sK + (txS + 16) * 130;
            #pragma unroll 4
            for (int d = 0; d < DIM; d += 2) {
                u64 k0 = *(const u64*)(kb0 + d);
                u64 k1 = *(const u64*)(kb1 + d);
                #pragma unroll
                for (int i = 0; i < 4; i++) {
                    u64 q = *(const u64*)(qb + i * 130 + d);
                    ffma2(s2[i][0], q, k0);
                    ffma2(s2[i][1], q, k1);
                }
            }
        }
        float p[4][2];
        #pragma unroll
        for (int i = 0; i < 4; i++) {
            p[i][0] = lo_plus_hi(s2[i][0]);
            p[i][1] = lo_plus_hi(s2[i][1]);
        }

        // Causal mask on the diagonal tile (local col > local row)
        if (kt == qt) {
            #pragma unroll
            for (int i = 0; i < 4; i++) {
                int rl = tyS * 4 + i;
                if (txS      > rl) p[i][0] = -1e30f;
                if (txS + 16 > rl) p[i][1] = -1e30f;
            }
        }

        // Online softmax, register + width-16 shuffles (row = 16 consecutive lanes)
        const int row0 = tyS * 4;
        #pragma unroll
        for (int i = 0; i < 4; i++) {
            float m = rmax16(fmaxf(p[i][0], p[i][1]));
            float mold = sM[row0 + i];
            float mnew = fmaxf(mold, m);
            float a  = __expf(mold - mnew);
            float e0 = __expf(p[i][0] - mnew);
            float e1 = __expf(p[i][1] - mnew);
            float l  = rsum16(e0 + e1);
            if (txS == 0) {
                sM[row0 + i] = mnew;
                sA[row0 + i] = a;
                sL[row0 + i] = sL[row0 + i] * a + l;
            }
            sS[(row0 + i) * 32 + txS]      = e0;
            sS[(row0 + i) * 32 + txS + 16] = e1;
        }
        __syncthreads();

        // Rescale accumulators by alpha
        #pragma unroll
        for (int i = 0; i < 8; i++) {
            u64 a2 = pack2(sA[ry * 8 + i]);
            #pragma unroll
            for (int j = 0; j < 4; j++) acc2[i][j] = fmul2(acc2[i][j], a2);
        }

        // O += P @ V, packed along c. 8 rows x 4 strided d-cols per thread.
        {
            const float* pb = sS + (ry * 8) * 32;
            #pragma unroll 2
            for (int c = 0; c < BN; c += 2) {
                u64 v2[4];
                #pragma unroll
                for (int j = 0; j < 4; j++)
                    v2[j] = *(const u64*)(sVt + (cx + 32 * j) * 34 + c);
                #pragma unroll
                for (int i = 0; i < 8; i++) {
                    u64 pp = *(const u64*)(pb + i * 32 + c);
                    #pragma unroll
                    for (int j = 0; j < 4; j++) ffma2(acc2[i][j], pp, v2[j]);
                }
            }
        }
    }

    // Epilogue: fold packed halves, normalize, write (coalesced along cx)
    float* ob = out + ((size_t)b * SEQ + qbase + ry * 8) * DIM;
    #pragma unroll
    for (int i = 0; i < 8; i++) {
        float inv = 1.0f / sL[ry * 8 + i];
        #pragma unroll
        for (int j = 0; j < 4; j++)
            ob[i * DIM + cx + 32 * j] = lo_plus_hi(acc2[i][j]) * inv;
    }
}

// ---------------------------------------------------------------------------
extern "C" void kernel_launch(void* const* d_in, const int* in_sizes, int n_in,
                              void* d_out, int out_size) {
    const float* x  = (const float*)d_in[0];
    const float* Wk = (const float*)d_in[1];
    const float* Wq = (const float*)d_in[2];
    const float* Wv = (const float*)d_in[3];
    float* out = (float*)d_out;

    const size_t qkv_smem  = (size_t)(DIM * DIM + QBM * DIM) * sizeof(float);  // 98304
    const size_t attn_smem = (size_t)(13792) * sizeof(float);                  // 55168

    cudaFuncSetAttribute(qkv_kernel,  cudaFuncAttributeMaxDynamicSharedMemorySize, (int)qkv_smem);
    cudaFuncSetAttribute(attn_kernel, cudaFuncAttributeMaxDynamicSharedMemorySize, (int)attn_smem);

    dim3 qkv_grid(SEQ / QBM, BATCH, 3);
    qkv_kernel<<<qkv_grid, 256, qkv_smem>>>(x, Wk, Wq, Wv);

    attn_kernel<<<NITEMS, ATHREADS, attn_smem>>>(out);
}

// round 4
// speedup vs baseline: 1.0031x; 1.0031x over previous
#include <cuda_runtime.h>
#include <math.h>

#define BATCH 8
#define SEQ   2048
#define DIM   128

// attention tiling
#define BM 32
#define BN 32
#define NQT (SEQ / BM)           // 64
#define NITEMS (NQT * BATCH)     // 512
#define ATHREADS 128

// qkv tiling
#define QBM 64

// Scratch (device globals — no allocation allowed)
__device__ float g_q[BATCH * SEQ * DIM];        // [b][t][d]
__device__ float g_k[BATCH * SEQ * DIM];        // [b][t][d]
__device__ float g_vt[BATCH * DIM * SEQ];       // [b][d][t]  (transposed V)

typedef unsigned long long u64;

__device__ __forceinline__ void ffma2(u64& d, u64 a, u64 b) {
    asm("fma.rn.f32x2 %0, %1, %2, %3;" : "=l"(d) : "l"(a), "l"(b), "l"(d));
}
__device__ __forceinline__ u64 fmul2(u64 a, u64 b) {
    u64 r; asm("mul.rn.f32x2 %0, %1, %2;" : "=l"(r) : "l"(a), "l"(b)); return r;
}
__device__ __forceinline__ u64 pack2(float x) {
    u64 r; asm("mov.b64 %0, {%1, %1};" : "=l"(r) : "f"(x)); return r;
}
__device__ __forceinline__ float lo_plus_hi(u64 v) {
    float2 f = *reinterpret_cast<float2*>(&v);
    return f.x + f.y;
}
__device__ __forceinline__ float rmax16(float v) {
    v = fmaxf(v, __shfl_xor_sync(0xffffffffu, v, 1));
    v = fmaxf(v, __shfl_xor_sync(0xffffffffu, v, 2));
    v = fmaxf(v, __shfl_xor_sync(0xffffffffu, v, 4));
    v = fmaxf(v, __shfl_xor_sync(0xffffffffu, v, 8));
    return v;
}
__device__ __forceinline__ float rsum16(float v) {
    v += __shfl_xor_sync(0xffffffffu, v, 1);
    v += __shfl_xor_sync(0xffffffffu, v, 2);
    v += __shfl_xor_sync(0xffffffffu, v, 4);
    v += __shfl_xor_sync(0xffffffffu, v, 8);
    return v;
}
// store a float4 to an 8B-aligned (possibly not 16B-aligned) smem row
__device__ __forceinline__ void st4_as_2x2(float* p, float4 v) {
    *(float2*)(p)     = make_float2(v.x, v.y);
    *(float2*)(p + 2) = make_float2(v.z, v.w);
}

// ---------------------------------------------------------------------------
// QKV projection: y[b,t,d] = sum_c x[b,t,c] * W[d,c]
// grid (SEQ/QBM, BATCH, 3), block 256.
// which==0 -> g_q natural, which==1 -> g_k natural, which==2 -> g_vt transposed
// ---------------------------------------------------------------------------
__global__ __launch_bounds__(256, 1)
void qkv_kernel(const float* __restrict__ x,
                const float* __restrict__ Wk,
                const float* __restrict__ Wq,
                const float* __restrict__ Wv) {
    extern __shared__ float sm[];
    float* sWt = sm;               // [DIM][DIM] : sWt[c*DIM + d]
    float* sX  = sm + DIM * DIM;   // [QBM][DIM]

    const int tq    = blockIdx.x;
    const int b     = blockIdx.y;
    const int which = blockIdx.z;
    const float* W  = (which == 0) ? Wq : (which == 1) ? Wk : Wv;
    const int tid = threadIdx.x;

    // Load W transposed into SMEM
    {
        int d  = tid >> 1;
        int c0 = (tid & 1) * 64;
        const float4* src = (const float4*)(W + d * DIM + c0);
        #pragma unroll
        for (int i = 0; i < 16; i++) {
            float4 w = src[i];
            int c = c0 + i * 4;
            sWt[(c + 0) * DIM + d] = w.x;
            sWt[(c + 1) * DIM + d] = w.y;
            sWt[(c + 2) * DIM + d] = w.z;
            sWt[(c + 3) * DIM + d] = w.w;
        }
    }
    // Load x tile [64][128]  (stride 128 -> float4 OK)
    {
        const float4* src = (const float4*)(x + ((size_t)b * SEQ + tq * QBM) * DIM);
        float4* dst = (float4*)sX;
        #pragma unroll
        for (int i = 0; i < 8; i++)
            dst[tid + i * 256] = src[tid + i * 256];
    }
    __syncthreads();

    const int cx = tid & 31;   // 4 output cols d = 4*cx..
    const int ry = tid >> 5;   // 8 output rows r = ry*8..
    float acc[8][4];
    #pragma unroll
    for (int i = 0; i < 8; i++)
        #pragma unroll
        for (int j = 0; j < 4; j++) acc[i][j] = 0.f;

    #pragma unroll 4
    for (int c = 0; c < DIM; c++) {
        float4 w = *(const float4*)(sWt + c * DIM + cx * 4);
        #pragma unroll
        for (int i = 0; i < 8; i++) {
            float xv = sX[(ry * 8 + i) * DIM + c];
            acc[i][0] += xv * w.x;
            acc[i][1] += xv * w.y;
            acc[i][2] += xv * w.z;
            acc[i][3] += xv * w.w;
        }
    }

    if (which != 2) {
        float* out = (which == 0) ? g_q : g_k;
        float* obase = out + ((size_t)b * SEQ + tq * QBM) * DIM;
        #pragma unroll
        for (int i = 0; i < 8; i++) {
            float4 o = make_float4(acc[i][0], acc[i][1], acc[i][2], acc[i][3]);
            *(float4*)(obase + (ry * 8 + i) * DIM + cx * 4) = o;
        }
    } else {
        // Stage tile in smem, then write transposed (coalesced along t) to g_vt
        __syncthreads();              // everyone done reading sWt/sX
        float* sOut = sm;             // [QBM][130] (stride 130: use float2 stores)
        #pragma unroll
        for (int i = 0; i < 8; i++) {
            st4_as_2x2(sOut + (ry * 8 + i) * 130 + cx * 4,
                       make_float4(acc[i][0], acc[i][1], acc[i][2], acc[i][3]));
        }
        __syncthreads();
        int dr = tid >> 1;            // d row 0..127
        int t0 = (tid & 1) * 32;      // half of the 64 tokens
        float* gbase = g_vt + ((size_t)b * DIM + dr) * SEQ + tq * QBM + t0;
        #pragma unroll
        for (int k4 = 0; k4 < 8; k4++) {
            float4 o;
            o.x = sOut[(t0 + k4 * 4 + 0) * 130 + dr];
            o.y = sOut[(t0 + k4 * 4 + 1) * 130 + dr];
            o.z = sOut[(t0 + k4 * 4 + 2) * 130 + dr];
            o.w = sOut[(t0 + k4 * 4 + 3) * 130 + dr];
            *(float4*)(gbase + k4 * 4) = o;
        }
    }
}

// ---------------------------------------------------------------------------
// Flash attention, fp32, packed f32x2 math. 128 threads, BM=BN=32.
// 4 CTAs/SM. Snake work ordering for per-SM balance (placement = LUT[bid%148]).
// ---------------------------------------------------------------------------
__global__ __launch_bounds__(ATHREADS, 4)
void attn_kernel(float* __restrict__ out) {
    extern __shared__ float sm[];
    float* sQ  = sm;            // [32][130]
    float* sK  = sm + 4160;     // [32][130]
    float* sVt = sm + 8320;     // [128][34]
    float* sS  = sm + 12672;    // [32][32]
    float* sM  = sm + 13696;    // [32]
    float* sL  = sm + 13728;    // [32]
    float* sA  = sm + 13760;    // [32]

    const int tid = threadIdx.x;

    // snake ordering: co-resident bids are b, b+148, b+296, b+444
    const int s_ = blockIdx.x % 148;
    const int o_ = blockIdx.x / 148;
    const int idx = (o_ == 0) ? s_
                  : (o_ == 1) ? (295 - s_)
                  : (o_ == 2) ? (296 + s_)
                  :             (511 - s_);
    const int qt = (NQT - 1) - (idx >> 3);   // heavy first
    const int b  = idx & 7;
    const int qbase = qt * BM;

    const float scale = 0.08838834764831845f;   // 1/sqrt(128)

    // Load Q tile (pre-scaled): [32][128] -> sQ[32][130]
    {
        const float* Qg = g_q + ((size_t)b * SEQ + qbase) * DIM;
        #pragma unroll
        for (int k = 0; k < 8; k++) {
            int i4 = tid + k * 128;
            int r = i4 >> 5, dc = (i4 & 31) * 4;
            float4 v = *(const float4*)(Qg + r * DIM + dc);
            v.x *= scale; v.y *= scale; v.z *= scale; v.w *= scale;
            st4_as_2x2(sQ + r * 130 + dc, v);
        }
    }
    if (tid < BM) { sM[tid] = -1e30f; sL[tid] = 0.f; }

    const int txS = tid & 15;   // S cols: txS, txS+16
    const int tyS = tid >> 4;   // S rows: tyS*4 + i (i<4)
    const int cx  = tid & 31;   // O cols: cx + 32*j (j<4)
    const int ry  = tid >> 5;   // O rows: ry*8 + i (i<8)

    u64 acc2[8][4];
    #pragma unroll
    for (int i = 0; i < 8; i++)
        #pragma unroll
        for (int j = 0; j < 4; j++) acc2[i][j] = 0ull;

    const float* Kg = g_k  + (size_t)b * SEQ * DIM;
    const float* Vg = g_vt + (size_t)b * DIM * SEQ;

    for (int kt = 0; kt <= qt; kt++) {
        __syncthreads();   // previous PV done with sS/sVt; prev softmax done with sM

        // K tile [32][128] -> sK[32][130]
        #pragma unroll
        for (int k = 0; k < 8; k++) {
            int i4 = tid + k * 128;
            int r = i4 >> 5, dc = (i4 & 31) * 4;
            float4 v = *(const float4*)(Kg + ((size_t)(kt * BN + r)) * DIM + dc);
            st4_as_2x2(sK + r * 130 + dc, v);
        }
        // Vt tile [128][32] -> sVt[128][34]
        #pragma unroll
        for (int k = 0; k < 8; k++) {
            int i4 = tid + k * 128;
            int dr = i4 >> 3, cc = (i4 & 7) * 4;
            float4 v = *(const float4*)(Vg + (size_t)dr * SEQ + kt * BN + cc);
            st4_as_2x2(sVt + dr * 34 + cc, v);
        }
        __syncthreads();

        // S = Q @ K^T, packed along d (reduction). 4 rows x 2 cols per thread.
        u64 s2[4][2];
        #pragma unroll
        for (int i = 0; i < 4; i++) { s2[i][0] = 0ull; s2[i][1] = 0ull; }
        {
            const float* qb  = sQ + (tyS * 4) * 130;
            const float* kb0 = sK + txS * 130;
            const float* kb1 = sK + (txS + 16) * 130;
            #pragma unroll 4
            for (int d = 0; d < DIM; d += 2) {
                u64 k0 = *(const u64*)(kb0 + d);
                u64 k1 = *(const u64*)(kb1 + d);
                #pragma unroll
                for (int i = 0; i < 4; i++) {
                    u64 q = *(const u64*)(qb + i * 130 + d);
                    ffma2(s2[i][0], q, k0);
                    ffma2(s2[i][1], q, k1);
                }
            }
        }
        float p[4][2];
        #pragma unroll
        for (int i = 0; i < 4; i++) {
            p[i][0] = lo_plus_hi(s2[i][0]);
            p[i][1] = lo_plus_hi(s2[i][1]);
        }

        // Causal mask on the diagonal tile (local col > local row)
        if (kt == qt) {
            #pragma unroll
            for (int i = 0; i < 4; i++) {
                int rl = tyS * 4 + i;
                if (txS      > rl) p[i][0] = -1e30f;
                if (txS + 16 > rl) p[i][1] = -1e30f;
            }
        }

        // Online softmax, register + width-16 shuffles (row = 16 consecutive lanes)
        const int row0 = tyS * 4;
        #pragma unroll
        for (int i = 0; i < 4; i++) {
            float m = rmax16(fmaxf(p[i][0], p[i][1]));
            float mold = sM[row0 + i];
            float mnew = fmaxf(mold, m);
            float a  = __expf(mold - mnew);
            float e0 = __expf(p[i][0] - mnew);
            float e1 = __expf(p[i][1] - mnew);
            float l  = rsum16(e0 + e1);
            if (txS == 0) {
                sM[row0 + i] = mnew;
                sA[row0 + i] = a;
                sL[row0 + i] = sL[row0 + i] * a + l;
            }
            sS[(row0 + i) * 32 + txS]      = e0;
            sS[(row0 + i) * 32 + txS + 16] = e1;
        }
        __syncthreads();

        // Rescale accumulators by alpha
        #pragma unroll
        for (int i = 0; i < 8; i++) {
            u64 a2 = pack2(sA[ry * 8 + i]);
            #pragma unroll
            for (int j = 0; j < 4; j++) acc2[i][j] = fmul2(acc2[i][j], a2);
        }

        // O += P @ V, packed along c. 8 rows x 4 strided d-cols per thread.
        {
            const float* pb = sS + (ry * 8) * 32;
            #pragma unroll 2
            for (int c = 0; c < BN; c += 2) {
                u64 v2[4];
                #pragma unroll
                for (int j = 0; j < 4; j++)
                    v2[j] = *(const u64*)(sVt + (cx + 32 * j) * 34 + c);
                #pragma unroll
                for (int i = 0; i < 8; i++) {
                    u64 pp = *(const u64*)(pb + i * 32 + c);
                    #pragma unroll
                    for (int j = 0; j < 4; j++) ffma2(acc2[i][j], pp, v2[j]);
                }
            }
        }
    }

    // Epilogue: fold packed halves, normalize, write (coalesced along cx)
    float* ob = out + ((size_t)b * SEQ + qbase + ry * 8) * DIM;
    #pragma unroll
    for (int i = 0; i < 8; i++) {
        float inv = 1.0f / sL[ry * 8 + i];
        #pragma unroll
        for (int j = 0; j < 4; j++)
            ob[i * DIM + cx + 32 * j] = lo_plus_hi(acc2[i][j]) * inv;
    }
}

// ---------------------------------------------------------------------------
extern "C" void kernel_launch(void* const* d_in, const int* in_sizes, int n_in,
                              void* d_out, int out_size) {
    const float* x  = (const float*)d_in[0];
    const float* Wk = (const float*)d_in[1];
    const float* Wq = (const float*)d_in[2];
    const float* Wv = (const float*)d_in[3];
    float* out = (float*)d_out;

    const size_t qkv_smem  = (size_t)(DIM * DIM + QBM * DIM) * sizeof(float);  // 98304
    const size_t attn_smem = (size_t)(13792) * sizeof(float);                  // 55168

    cudaFuncSetAttribute(qkv_kernel,  cudaFuncAttributeMaxDynamicSharedMemorySize, (int)qkv_smem);
    cudaFuncSetAttribute(attn_kernel, cudaFuncAttributeMaxDynamicSharedMemorySize, (int)attn_smem);

    dim3 qkv_grid(SEQ / QBM, BATCH, 3);
    qkv_kernel<<<qkv_grid, 256, qkv_smem>>>(x, Wk, Wq, Wv);

    attn_kernel<<<NITEMS, ATHREADS, attn_smem>>>(out);
}

// round 12
// speedup vs baseline: 2.2171x; 2.2102x over previous
#include <cuda_runtime.h>
#include <cuda_bf16.h>
#include <math.h>
#include <cstdint>

#define BATCH 8
#define SEQ   2048
#define DIM   128
#define QBM   64            // qkv token tile
#define ABM   128           // attention q rows per CTA
#define ABN   64            // keys per iteration
#define NQT   (SEQ / ABM)   // 16

// SMEM byte offsets (attention kernel)
#define SQH 0               // Q hi  [128][136] bf16 (272B rows)
#define SQL 34816           // Q lo
#define SKH 69632           // K hi  [64][136]
#define SKL 87040           // K lo
#define SVH 104448          // V^T hi [128][72] (144B rows)
#define SVL 122880          // V^T lo
#define SMEM_ATTN 141312

// Scratch (device globals — no allocation allowed)
__device__ __nv_bfloat16 g_qh[BATCH * SEQ * DIM];
__device__ __nv_bfloat16 g_ql[BATCH * SEQ * DIM];
__device__ __nv_bfloat16 g_kh[BATCH * SEQ * DIM];
__device__ __nv_bfloat16 g_kl[BATCH * SEQ * DIM];
__device__ __nv_bfloat16 g_vth[BATCH * DIM * SEQ];   // [b][d][t]
__device__ __nv_bfloat16 g_vtl[BATCH * DIM * SEQ];

__device__ __forceinline__ uint32_t smem_u32(const void* p) {
    uint32_t a;
    asm("{ .reg .u64 t; cvta.to.shared.u64 t, %1; cvt.u32.u64 %0, t; }" : "=r"(a) : "l"(p));
    return a;
}
__device__ __forceinline__ float ex2f(float x) {
    float r; asm("ex2.approx.ftz.f32 %0, %1;" : "=f"(r) : "f"(x)); return r;
}

#define LDSM4(r0, r1, r2, r3, addr) \
    asm volatile("ldmatrix.sync.aligned.m8n8.x4.shared.b16 {%0,%1,%2,%3}, [%4];" \
        : "=r"(r0), "=r"(r1), "=r"(r2), "=r"(r3) : "r"(addr))
#define LDSM2(r0, r1, addr) \
    asm volatile("ldmatrix.sync.aligned.m8n8.x2.shared.b16 {%0,%1}, [%2];" \
        : "=r"(r0), "=r"(r1) : "r"(addr))
#define MMA16816(c, a0, a1, a2, a3, b0, b1) \
    asm volatile("mma.sync.aligned.m16n8k16.row.col.f32.bf16.bf16.f32 " \
        "{%0,%1,%2,%3}, {%4,%5,%6,%7}, {%8,%9}, {%0,%1,%2,%3};" \
        : "+f"((c)[0]), "+f"((c)[1]), "+f"((c)[2]), "+f"((c)[3]) \
        : "r"(a0), "r"(a1), "r"(a2), "r"(a3), "r"(b0), "r"(b1))

// split fp32 pair into bf16x2 hi + bf16x2 lo
__device__ __forceinline__ void hilo2(float x, float y, uint32_t& h, uint32_t& l) {
    __nv_bfloat162 hp = __float22bfloat162_rn(make_float2(x, y));
    float2 hf = __bfloat1622float2(hp);
    __nv_bfloat162 lp = __float22bfloat162_rn(make_float2(x - hf.x, y - hf.y));
    h = *(uint32_t*)&hp;
    l = *(uint32_t*)&lp;
}
__device__ __forceinline__ void split4(float4 a, uint2& h, uint2& l) {
    uint32_t h0, l0, h1, l1;
    hilo2(a.x, a.y, h0, l0);
    hilo2(a.z, a.w, h1, l1);
    h.x = h0; h.y = h1; l.x = l0; l.y = l1;
}
__device__ __forceinline__ void st4_as_2x2(float* p, float4 v) {
    *(float2*)(p)     = make_float2(v.x, v.y);
    *(float2*)(p + 2) = make_float2(v.z, v.w);
}

// ---------------------------------------------------------------------------
// QKV projection + bf16 hi/lo split outputs. grid (32, 8, 3), block 256.
// ---------------------------------------------------------------------------
__global__ __launch_bounds__(256, 1)
void qkv_kernel(const float* __restrict__ x, const float* __restrict__ Wk,
                const float* __restrict__ Wq, const float* __restrict__ Wv) {
    extern __shared__ float sm[];
    float* sWt = sm;               // [128][128] W^T
    float* sX  = sm + DIM * DIM;   // [64][128]

    const int tq = blockIdx.x, b = blockIdx.y, which = blockIdx.z;
    const float* W = (which == 0) ? Wq : (which == 1) ? Wk : Wv;
    const int tid = threadIdx.x;

    {   // W transposed into SMEM
        int d = tid >> 1, c0 = (tid & 1) * 64;
        const float4* src = (const float4*)(W + d * DIM + c0);
        #pragma unroll
        for (int i = 0; i < 16; i++) {
            float4 w = src[i]; int c = c0 + i * 4;
            sWt[(c + 0) * DIM + d] = w.x; sWt[(c + 1) * DIM + d] = w.y;
            sWt[(c + 2) * DIM + d] = w.z; sWt[(c + 3) * DIM + d] = w.w;
        }
    }
    {   // x tile
        const float4* src = (const float4*)(x + ((size_t)b * SEQ + tq * QBM) * DIM);
        float4* dst = (float4*)sX;
        #pragma unroll
        for (int i = 0; i < 8; i++) dst[tid + i * 256] = src[tid + i * 256];
    }
    __syncthreads();

    const int cx = tid & 31, ry = tid >> 5;
    float acc[8][4];
    #pragma unroll
    for (int i = 0; i < 8; i++)
        #pragma unroll
        for (int j = 0; j < 4; j++) acc[i][j] = 0.f;

    #pragma unroll 4
    for (int c = 0; c < DIM; c++) {
        float4 w = *(const float4*)(sWt + c * DIM + cx * 4);
        #pragma unroll
        for (int i = 0; i < 8; i++) {
            float xv = sX[(ry * 8 + i) * DIM + c];
            acc[i][0] += xv * w.x; acc[i][1] += xv * w.y;
            acc[i][2] += xv * w.z; acc[i][3] += xv * w.w;
        }
    }

    if (which == 0) {   // Q: pre-scale by log2e/sqrt(128), split
        const float QS = 0.08838834764831845f * 1.4426950408889634f;
        size_t rowbase = (size_t)b * SEQ + tq * QBM;
        #pragma unroll
        for (int i = 0; i < 8; i++) {
            size_t g = (rowbase + ry * 8 + i) * DIM + cx * 4;
            float4 a = make_float4(acc[i][0]*QS, acc[i][1]*QS, acc[i][2]*QS, acc[i][3]*QS);
            uint2 h, l; split4(a, h, l);
            *(uint2*)(g_qh + g) = h; *(uint2*)(g_ql + g) = l;
        }
    } else if (which == 1) {   // K: split
        size_t rowbase = (size_t)b * SEQ + tq * QBM;
        #pragma unroll
        for (int i = 0; i < 8; i++) {
            size_t g = (rowbase + ry * 8 + i) * DIM + cx * 4;
            float4 a = make_float4(acc[i][0], acc[i][1], acc[i][2], acc[i][3]);
            uint2 h, l; split4(a, h, l);
            *(uint2*)(g_kh + g) = h; *(uint2*)(g_kl + g) = l;
        }
    } else {   // V: transpose via SMEM stage, split
        __syncthreads();
        float* sOut = sm;   // [64][130]
        #pragma unroll
        for (int i = 0; i < 8; i++)
            st4_as_2x2(sOut + (ry * 8 + i) * 130 + cx * 4,
                       make_float4(acc[i][0], acc[i][1], acc[i][2], acc[i][3]));
        __syncthreads();
        int dr = tid >> 1, t0 = (tid & 1) * 32;
        size_t gb = ((size_t)b * DIM + dr) * SEQ + tq * QBM + t0;
        #pragma unroll
        for (int k4 = 0; k4 < 8; k4++) {
            float4 v = make_float4(sOut[(t0 + k4*4 + 0) * 130 + dr],
                                   sOut[(t0 + k4*4 + 1) * 130 + dr],
                                   sOut[(t0 + k4*4 + 2) * 130 + dr],
                                   sOut[(t0 + k4*4 + 3) * 130 + dr]);
            uint2 h, l; split4(v, h, l);
            *(uint2*)(g_vth + gb + k4*4) = h;
            *(uint2*)(g_vtl + gb + k4*4) = l;
        }
    }
}

// ---------------------------------------------------------------------------
// Warp-MMA flash attention, fixed-offset softmax, bf16 2-term x 3 passes.
// 256 threads (8 warps x m16), BM=128 rows/CTA, BN=64 keys/iter.
// ---------------------------------------------------------------------------
__global__ __launch_bounds__(256, 1)
void attn_kernel(float* __restrict__ out) {
    extern __shared__ char smem[];
    const uint32_t sb = smem_u32(smem);
    const int tid = threadIdx.x, wid = tid >> 5, lane = tid & 31;
    const int qt = (NQT - 1) - (blockIdx.x >> 3);   // heavy tiles first
    const int b  = blockIdx.x & 7;
    const int qbase = qt * ABM;
    const int m0 = wid * 16;
    const int g  = lane >> 2;            // fragment row within 8
    const int q2 = (lane & 3) * 2;       // fragment col pair
    const int nk = 2 * (qt + 1);         // 64-key tiles to process

    // ---- load Q tile (hi/lo) into SMEM [128][136] ----
    {
        const __nv_bfloat16* qh = g_qh + ((size_t)b * SEQ + qbase) * DIM;
        const __nv_bfloat16* ql = g_ql + ((size_t)b * SEQ + qbase) * DIM;
        #pragma unroll
        for (int j = 0; j < 8; j++) {
            int i = tid + j * 256;
            int r = i >> 4, cs = i & 15;
            *(uint4*)(smem + SQH + r * 272 + cs * 16) = *(const uint4*)(qh + r * DIM + cs * 8);
            *(uint4*)(smem + SQL + r * 272 + cs * 16) = *(const uint4*)(ql + r * DIM + cs * 8);
        }
    }

    // ldmatrix per-lane base addresses
    const int aRow = m0 + (lane & 7) + ((lane >> 3) & 1) * 8;
    const int aCol = ((lane >> 4) & 1) * 16;
    const uint32_t aQH = sb + SQH + aRow * 272 + aCol;
    const uint32_t aQL = sb + SQL + aRow * 272 + aCol;
    const int bRow = (lane & 7);
    const int bCol = (((lane & 15) >> 3) & 1) * 16;
    const uint32_t bKH = sb + SKH + bRow * 272 + bCol;
    const uint32_t bKL = sb + SKL + bRow * 272 + bCol;
    const uint32_t bVH = sb + SVH + bRow * 144 + bCol;
    const uint32_t bVL = sb + SVL + bRow * 144 + bCol;

    float o[16][4];
    #pragma unroll
    for (int nt = 0; nt < 16; nt++)
        #pragma unroll
        for (int j = 0; j < 4; j++) o[nt][j] = 0.f;
    float ls0 = 0.f, ls1 = 0.f;

    const __nv_bfloat16* Kh = g_kh + (size_t)b * SEQ * DIM;
    const __nv_bfloat16* Kl = g_kl + (size_t)b * SEQ * DIM;
    const __nv_bfloat16* Vh = g_vth + (size_t)b * DIM * SEQ;
    const __nv_bfloat16* Vl = g_vtl + (size_t)b * DIM * SEQ;

    for (int kt = 0; kt < nk; kt++) {
        const int kb = kt * ABN;
        __syncthreads();
        // K tiles [64][128] -> [64][136]
        #pragma unroll
        for (int j = 0; j < 4; j++) {
            int i = tid + j * 256;
            int r = i >> 4, cs = i & 15;
            *(uint4*)(smem + SKH + r * 272 + cs * 16) =
                *(const uint4*)(Kh + (size_t)(kb + r) * DIM + cs * 8);
            *(uint4*)(smem + SKL + r * 272 + cs * 16) =
                *(const uint4*)(Kl + (size_t)(kb + r) * DIM + cs * 8);
        }
        // V^T tiles [128][64] -> [128][72]
        #pragma unroll
        for (int j = 0; j < 4; j++) {
            int i = tid + j * 256;
            int d = i >> 3, cs = i & 7;
            *(uint4*)(smem + SVH + d * 144 + cs * 16) =
                *(const uint4*)(Vh + (size_t)d * SEQ + kb + cs * 8);
            *(uint4*)(smem + SVL + d * 144 + cs * 16) =
                *(const uint4*)(Vl + (size_t)d * SEQ + kb + cs * 8);
        }
        __syncthreads();

        // ---- S = Q K^T (3 passes fused per k-step) ----
        float s[8][4];
        #pragma unroll
        for (int nt = 0; nt < 8; nt++)
            #pragma unroll
            for (int j = 0; j < 4; j++) s[nt][j] = 0.f;

        #pragma unroll
        for (int k8 = 0; k8 < 8; k8++) {
            uint32_t ah[4], al[4];
            LDSM4(ah[0], ah[1], ah[2], ah[3], aQH + k8 * 32);
            LDSM4(al[0], al[1], al[2], al[3], aQL + k8 * 32);
            #pragma unroll
            for (int nt = 0; nt < 8; nt++) {
                uint32_t bh0, bh1, bl0, bl1;
                LDSM2(bh0, bh1, bKH + nt * 2176 + k8 * 32);
                LDSM2(bl0, bl1, bKL + nt * 2176 + k8 * 32);
                MMA16816(s[nt], ah[0], ah[1], ah[2], ah[3], bh0, bh1);
                MMA16816(s[nt], ah[0], ah[1], ah[2], ah[3], bl0, bl1);
                MMA16816(s[nt], al[0], al[1], al[2], al[3], bh0, bh1);
            }
        }

        // ---- mask + exp2(s - 17.3125) + lsum ----
        const float OFF = 17.3125f;
        const bool nm = (kb + ABN - 1) > (qbase + m0);
        const int r0 = qbase + m0 + g, r1 = r0 + 8;
        #pragma unroll
        for (int nt = 0; nt < 8; nt++) {
            if (nm) {
                int c0 = kb + nt * 8 + q2;
                s[nt][0] = (c0     <= r0) ? ex2f(s[nt][0] - OFF) : 0.f;
                s[nt][1] = (c0 + 1 <= r0) ? ex2f(s[nt][1] - OFF) : 0.f;
                s[nt][2] = (c0     <= r1) ? ex2f(s[nt][2] - OFF) : 0.f;
                s[nt][3] = (c0 + 1 <= r1) ? ex2f(s[nt][3] - OFF) : 0.f;
            } else {
                s[nt][0] = ex2f(s[nt][0] - OFF);
                s[nt][1] = ex2f(s[nt][1] - OFF);
                s[nt][2] = ex2f(s[nt][2] - OFF);
                s[nt][3] = ex2f(s[nt][3] - OFF);
            }
            ls0 += s[nt][0] + s[nt][1];
            ls1 += s[nt][2] + s[nt][3];
        }

        // ---- repack P C-frags -> A-frags (hi/lo) ----
        uint32_t ph[4][4], pl[4][4];
        #pragma unroll
        for (int kk = 0; kk < 4; kk++) {
            int n0 = 2 * kk, n1 = 2 * kk + 1;
            hilo2(s[n0][0], s[n0][1], ph[kk][0], pl[kk][0]);
            hilo2(s[n0][2], s[n0][3], ph[kk][1], pl[kk][1]);
            hilo2(s[n1][0], s[n1][1], ph[kk][2], pl[kk][2]);
            hilo2(s[n1][2], s[n1][3], ph[kk][3], pl[kk][3]);
        }

        // ---- O += P V (3 passes fused per B load) ----
        #pragma unroll
        for (int kk = 0; kk < 4; kk++) {
            #pragma unroll
            for (int nt = 0; nt < 16; nt++) {
                uint32_t vh0, vh1, vl0, vl1;
                LDSM2(vh0, vh1, bVH + nt * 1152 + kk * 32);
                LDSM2(vl0, vl1, bVL + nt * 1152 + kk * 32);
                MMA16816(o[nt], ph[kk][0], ph[kk][1], ph[kk][2], ph[kk][3], vh0, vh1);
                MMA16816(o[nt], ph[kk][0], ph[kk][1], ph[kk][2], ph[kk][3], vl0, vl1);
                MMA16816(o[nt], pl[kk][0], pl[kk][1], pl[kk][2], pl[kk][3], vh0, vh1);
            }
        }
    }

    // ---- epilogue: quad-reduce lsum, normalize, store ----
    ls0 += __shfl_xor_sync(0xffffffffu, ls0, 1);
    ls0 += __shfl_xor_sync(0xffffffffu, ls0, 2);
    ls1 += __shfl_xor_sync(0xffffffffu, ls1, 1);
    ls1 += __shfl_xor_sync(0xffffffffu, ls1, 2);
    const float inv0 = 1.0f / ls0, inv1 = 1.0f / ls1;
    float* op = out + ((size_t)b * SEQ + qbase + m0) * DIM;
    #pragma unroll
    for (int nt = 0; nt < 16; nt++) {
        *(float2*)(op + (size_t)g * DIM + nt * 8 + q2) =
            make_float2(o[nt][0] * inv0, o[nt][1] * inv0);
        *(float2*)(op + (size_t)(g + 8) * DIM + nt * 8 + q2) =
            make_float2(o[nt][2] * inv1, o[nt][3] * inv1);
    }
}

// ---------------------------------------------------------------------------
extern "C" void kernel_launch(void* const* d_in, const int* in_sizes, int n_in,
                              void* d_out, int out_size) {
    const float* x  = (const float*)d_in[0];
    const float* Wk = (const float*)d_in[1];
    const float* Wq = (const float*)d_in[2];
    const float* Wv = (const float*)d_in[3];
    float* out = (float*)d_out;

    const size_t qkv_smem = (size_t)(DIM * DIM + QBM * DIM) * sizeof(float);  // 98304

    cudaFuncSetAttribute(qkv_kernel,  cudaFuncAttributeMaxDynamicSharedMemorySize, (int)qkv_smem);
    cudaFuncSetAttribute(attn_kernel, cudaFuncAttributeMaxDynamicSharedMemorySize, SMEM_ATTN);

    dim3 qkv_grid(SEQ / QBM, BATCH, 3);
    qkv_kernel<<<qkv_grid, 256, qkv_smem>>>(x, Wk, Wq, Wv);

    attn_kernel<<<NQT * BATCH, 256, SMEM_ATTN>>>(out);
}

// round 13
// speedup vs baseline: 2.7081x; 1.2215x over previous
#include <cuda_runtime.h>
#include <cuda_bf16.h>
#include <math.h>
#include <cstdint>

#define BATCH 8
#define SEQ   2048
#define DIM   128
#define QBM   64            // qkv token tile
#define ABM   64            // attention q rows per CTA
#define ABN   64            // keys per iteration
#define NQT   (SEQ / ABM)   // 32

// SMEM byte offsets (attention kernel)
#define SQH 0               // Q hi  [64][136] bf16 (272B rows)
#define SQL 17408           // Q lo
#define SKH 34816           // K hi  [64][136]
#define SKL 52224           // K lo
#define SVH 69632           // V^T hi [128][72] (144B rows)
#define SVL 88064           // V^T lo
#define SMEM_ATTN 106496

// Scratch (device globals — no allocation allowed)
__device__ __nv_bfloat16 g_qh[BATCH * SEQ * DIM];
__device__ __nv_bfloat16 g_ql[BATCH * SEQ * DIM];
__device__ __nv_bfloat16 g_kh[BATCH * SEQ * DIM];
__device__ __nv_bfloat16 g_kl[BATCH * SEQ * DIM];
__device__ __nv_bfloat16 g_vth[BATCH * DIM * SEQ];   // [b][d][t]
__device__ __nv_bfloat16 g_vtl[BATCH * DIM * SEQ];

__device__ __forceinline__ uint32_t smem_u32(const void* p) {
    uint32_t a;
    asm("{ .reg .u64 t; cvta.to.shared.u64 t, %1; cvt.u32.u64 %0, t; }" : "=r"(a) : "l"(p));
    return a;
}
__device__ __forceinline__ float ex2f(float x) {
    float r; asm("ex2.approx.ftz.f32 %0, %1;" : "=f"(r) : "f"(x)); return r;
}

#define LDSM4(r0, r1, r2, r3, addr) \
    asm volatile("ldmatrix.sync.aligned.m8n8.x4.shared.b16 {%0,%1,%2,%3}, [%4];" \
        : "=r"(r0), "=r"(r1), "=r"(r2), "=r"(r3) : "r"(addr))
#define LDSM2(r0, r1, addr) \
    asm volatile("ldmatrix.sync.aligned.m8n8.x2.shared.b16 {%0,%1}, [%2];" \
        : "=r"(r0), "=r"(r1) : "r"(addr))
#define MMA16816(c, a0, a1, a2, a3, b0, b1) \
    asm volatile("mma.sync.aligned.m16n8k16.row.col.f32.bf16.bf16.f32 " \
        "{%0,%1,%2,%3}, {%4,%5,%6,%7}, {%8,%9}, {%0,%1,%2,%3};" \
        : "+f"((c)[0]), "+f"((c)[1]), "+f"((c)[2]), "+f"((c)[3]) \
        : "r"(a0), "r"(a1), "r"(a2), "r"(a3), "r"(b0), "r"(b1))

// split fp32 pair into bf16x2 hi + bf16x2 lo
__device__ __forceinline__ void hilo2(float x, float y, uint32_t& h, uint32_t& l) {
    __nv_bfloat162 hp = __float22bfloat162_rn(make_float2(x, y));
    float2 hf = __bfloat1622float2(hp);
    __nv_bfloat162 lp = __float22bfloat162_rn(make_float2(x - hf.x, y - hf.y));
    h = *(uint32_t*)&hp;
    l = *(uint32_t*)&lp;
}
__device__ __forceinline__ void split4(float4 a, uint2& h, uint2& l) {
    uint32_t h0, l0, h1, l1;
    hilo2(a.x, a.y, h0, l0);
    hilo2(a.z, a.w, h1, l1);
    h.x = h0; h.y = h1; l.x = l0; l.y = l1;
}
__device__ __forceinline__ void st4_as_2x2(float* p, float4 v) {
    *(float2*)(p)     = make_float2(v.x, v.y);
    *(float2*)(p + 2) = make_float2(v.z, v.w);
}

// ---------------------------------------------------------------------------
// QKV projection + bf16 hi/lo split outputs. grid (32, 8, 3), block 256.
// ---------------------------------------------------------------------------
__global__ __launch_bounds__(256, 1)
void qkv_kernel(const float* __restrict__ x, const float* __restrict__ Wk,
                const float* __restrict__ Wq, const float* __restrict__ Wv) {
    extern __shared__ float sm[];
    float* sWt = sm;               // [128][128] W^T
    float* sX  = sm + DIM * DIM;   // [64][128]

    const int tq = blockIdx.x, b = blockIdx.y, which = blockIdx.z;
    const float* W = (which == 0) ? Wq : (which == 1) ? Wk : Wv;
    const int tid = threadIdx.x;

    {   // W transposed into SMEM
        int d = tid >> 1, c0 = (tid & 1) * 64;
        const float4* src = (const float4*)(W + d * DIM + c0);
        #pragma unroll
        for (int i = 0; i < 16; i++) {
            float4 w = src[i]; int c = c0 + i * 4;
            sWt[(c + 0) * DIM + d] = w.x; sWt[(c + 1) * DIM + d] = w.y;
            sWt[(c + 2) * DIM + d] = w.z; sWt[(c + 3) * DIM + d] = w.w;
        }
    }
    {   // x tile
        const float4* src = (const float4*)(x + ((size_t)b * SEQ + tq * QBM) * DIM);
        float4* dst = (float4*)sX;
        #pragma unroll
        for (int i = 0; i < 8; i++) dst[tid + i * 256] = src[tid + i * 256];
    }
    __syncthreads();

    const int cx = tid & 31, ry = tid >> 5;
    float acc[8][4];
    #pragma unroll
    for (int i = 0; i < 8; i++)
        #pragma unroll
        for (int j = 0; j < 4; j++) acc[i][j] = 0.f;

    #pragma unroll 4
    for (int c = 0; c < DIM; c++) {
        float4 w = *(const float4*)(sWt + c * DIM + cx * 4);
        #pragma unroll
        for (int i = 0; i < 8; i++) {
            float xv = sX[(ry * 8 + i) * DIM + c];
            acc[i][0] += xv * w.x; acc[i][1] += xv * w.y;
            acc[i][2] += xv * w.z; acc[i][3] += xv * w.w;
        }
    }

    if (which == 0) {   // Q: pre-scale by log2e/sqrt(128), split
        const float QS = 0.08838834764831845f * 1.4426950408889634f;
        size_t rowbase = (size_t)b * SEQ + tq * QBM;
        #pragma unroll
        for (int i = 0; i < 8; i++) {
            size_t g = (rowbase + ry * 8 + i) * DIM + cx * 4;
            float4 a = make_float4(acc[i][0]*QS, acc[i][1]*QS, acc[i][2]*QS, acc[i][3]*QS);
            uint2 h, l; split4(a, h, l);
            *(uint2*)(g_qh + g) = h; *(uint2*)(g_ql + g) = l;
        }
    } else if (which == 1) {   // K: split
        size_t rowbase = (size_t)b * SEQ + tq * QBM;
        #pragma unroll
        for (int i = 0; i < 8; i++) {
            size_t g = (rowbase + ry * 8 + i) * DIM + cx * 4;
            float4 a = make_float4(acc[i][0], acc[i][1], acc[i][2], acc[i][3]);
            uint2 h, l; split4(a, h, l);
            *(uint2*)(g_kh + g) = h; *(uint2*)(g_kl + g) = l;
        }
    } else {   // V: transpose via SMEM stage, split
        __syncthreads();
        float* sOut = sm;   // [64][130]
        #pragma unroll
        for (int i = 0; i < 8; i++)
            st4_as_2x2(sOut + (ry * 8 + i) * 130 + cx * 4,
                       make_float4(acc[i][0], acc[i][1], acc[i][2], acc[i][3]));
        __syncthreads();
        int dr = tid >> 1, t0 = (tid & 1) * 32;
        size_t gb = ((size_t)b * DIM + dr) * SEQ + tq * QBM + t0;
        #pragma unroll
        for (int k4 = 0; k4 < 8; k4++) {
            float4 v = make_float4(sOut[(t0 + k4*4 + 0) * 130 + dr],
                                   sOut[(t0 + k4*4 + 1) * 130 + dr],
                                   sOut[(t0 + k4*4 + 2) * 130 + dr],
                                   sOut[(t0 + k4*4 + 3) * 130 + dr]);
            uint2 h, l; split4(v, h, l);
            *(uint2*)(g_vth + gb + k4*4) = h;
            *(uint2*)(g_vtl + gb + k4*4) = l;
        }
    }
}

// ---------------------------------------------------------------------------
// Warp-MMA flash attention, fixed-offset softmax, bf16 2-term x 3 passes.
// 128 threads (4 warps x m16), BM=64 rows/CTA, BN=64 keys/iter.
// 2 CTAs/SM; heavy+light pairing across the two wave slots per SM.
// ---------------------------------------------------------------------------
__global__ __launch_bounds__(128, 2)
void attn_kernel(float* __restrict__ out) {
    extern __shared__ char smem[];
    const uint32_t sb = smem_u32(smem);
    const int tid = threadIdx.x, wid = tid >> 5, lane = tid & 31;

    // heavy+light pairing: bid and bid+148 land on the same SM (classic LUT).
    const int bid = blockIdx.x;
    const int idx = (bid < 148) ? bid : (403 - bid);   // 256 items total
    const int qt = (NQT - 1) - (idx >> 3);             // heaviest first
    const int b  = idx & 7;
    const int qbase = qt * ABM;
    const int m0 = wid * 16;
    const int g  = lane >> 2;            // fragment row within 8
    const int q2 = (lane & 3) * 2;       // fragment col pair
    const int nk = qt + 1;               // 64-key tiles to process

    // ---- load Q tile (hi/lo) into SMEM [64][136] ----
    {
        const __nv_bfloat16* qh = g_qh + ((size_t)b * SEQ + qbase) * DIM;
        const __nv_bfloat16* ql = g_ql + ((size_t)b * SEQ + qbase) * DIM;
        #pragma unroll
        for (int j = 0; j < 8; j++) {
            int i = tid + j * 128;
            int r = i >> 4, cs = i & 15;
            *(uint4*)(smem + SQH + r * 272 + cs * 16) = *(const uint4*)(qh + r * DIM + cs * 8);
            *(uint4*)(smem + SQL + r * 272 + cs * 16) = *(const uint4*)(ql + r * DIM + cs * 8);
        }
    }

    // ldmatrix per-lane base addresses
    const int aRow = m0 + (lane & 7) + ((lane >> 3) & 1) * 8;
    const int aCol = ((lane >> 4) & 1) * 16;
    const uint32_t aQH = sb + SQH + aRow * 272 + aCol;
    const uint32_t aQL = sb + SQL + aRow * 272 + aCol;
    const int bRow = (lane & 7);
    const int bCol = (((lane & 15) >> 3) & 1) * 16;
    const uint32_t bKH = sb + SKH + bRow * 272 + bCol;
    const uint32_t bKL = sb + SKL + bRow * 272 + bCol;
    const uint32_t bVH = sb + SVH + bRow * 144 + bCol;
    const uint32_t bVL = sb + SVL + bRow * 144 + bCol;

    float o[16][4];
    #pragma unroll
    for (int nt = 0; nt < 16; nt++)
        #pragma unroll
        for (int j = 0; j < 4; j++) o[nt][j] = 0.f;
    float ls0 = 0.f, ls1 = 0.f;

    const __nv_bfloat16* Kh = g_kh + (size_t)b * SEQ * DIM;
    const __nv_bfloat16* Kl = g_kl + (size_t)b * SEQ * DIM;
    const __nv_bfloat16* Vh = g_vth + (size_t)b * DIM * SEQ;
    const __nv_bfloat16* Vl = g_vtl + (size_t)b * DIM * SEQ;

    for (int kt = 0; kt < nk; kt++) {
        const int kb = kt * ABN;
        __syncthreads();
        // K tiles [64][128] -> [64][136]
        #pragma unroll
        for (int j = 0; j < 8; j++) {
            int i = tid + j * 128;
            int r = i >> 4, cs = i & 15;
            *(uint4*)(smem + SKH + r * 272 + cs * 16) =
                *(const uint4*)(Kh + (size_t)(kb + r) * DIM + cs * 8);
            *(uint4*)(smem + SKL + r * 272 + cs * 16) =
                *(const uint4*)(Kl + (size_t)(kb + r) * DIM + cs * 8);
        }
        // V^T tiles [128][64] -> [128][72]
        #pragma unroll
        for (int j = 0; j < 8; j++) {
            int i = tid + j * 128;
            int d = i >> 3, cs = i & 7;
            *(uint4*)(smem + SVH + d * 144 + cs * 16) =
                *(const uint4*)(Vh + (size_t)d * SEQ + kb + cs * 8);
            *(uint4*)(smem + SVL + d * 144 + cs * 16) =
                *(const uint4*)(Vl + (size_t)d * SEQ + kb + cs * 8);
        }
        __syncthreads();

        // ---- S = Q K^T (3 passes fused per k-step) ----
        float s[8][4];
        #pragma unroll
        for (int nt = 0; nt < 8; nt++)
            #pragma unroll
            for (int j = 0; j < 4; j++) s[nt][j] = 0.f;

        #pragma unroll
        for (int k8 = 0; k8 < 8; k8++) {
            uint32_t ah[4], al[4];
            LDSM4(ah[0], ah[1], ah[2], ah[3], aQH + k8 * 32);
            LDSM4(al[0], al[1], al[2], al[3], aQL + k8 * 32);
            #pragma unroll
            for (int nt = 0; nt < 8; nt++) {
                uint32_t bh0, bh1, bl0, bl1;
                LDSM2(bh0, bh1, bKH + nt * 2176 + k8 * 32);
                LDSM2(bl0, bl1, bKL + nt * 2176 + k8 * 32);
                MMA16816(s[nt], ah[0], ah[1], ah[2], ah[3], bh0, bh1);
                MMA16816(s[nt], ah[0], ah[1], ah[2], ah[3], bl0, bl1);
                MMA16816(s[nt], al[0], al[1], al[2], al[3], bh0, bh1);
            }
        }

        // ---- mask + exp2(s - 17.3125) + lsum ----
        const float OFF = 17.3125f;
        const bool nm = (kb + ABN - 1) > (qbase + m0);
        const int r0 = qbase + m0 + g, r1 = r0 + 8;
        #pragma unroll
        for (int nt = 0; nt < 8; nt++) {
            if (nm) {
                int c0 = kb + nt * 8 + q2;
                s[nt][0] = (c0     <= r0) ? ex2f(s[nt][0] - OFF) : 0.f;
                s[nt][1] = (c0 + 1 <= r0) ? ex2f(s[nt][1] - OFF) : 0.f;
                s[nt][2] = (c0     <= r1) ? ex2f(s[nt][2] - OFF) : 0.f;
                s[nt][3] = (c0 + 1 <= r1) ? ex2f(s[nt][3] - OFF) : 0.f;
            } else {
                s[nt][0] = ex2f(s[nt][0] - OFF);
                s[nt][1] = ex2f(s[nt][1] - OFF);
                s[nt][2] = ex2f(s[nt][2] - OFF);
                s[nt][3] = ex2f(s[nt][3] - OFF);
            }
            ls0 += s[nt][0] + s[nt][1];
            ls1 += s[nt][2] + s[nt][3];
        }

        // ---- repack P C-frags -> A-frags (hi/lo) ----
        uint32_t ph[4][4], pl[4][4];
        #pragma unroll
        for (int kk = 0; kk < 4; kk++) {
            int n0 = 2 * kk, n1 = 2 * kk + 1;
            hilo2(s[n0][0], s[n0][1], ph[kk][0], pl[kk][0]);
            hilo2(s[n0][2], s[n0][3], ph[kk][1], pl[kk][1]);
            hilo2(s[n1][0], s[n1][1], ph[kk][2], pl[kk][2]);
            hilo2(s[n1][2], s[n1][3], ph[kk][3], pl[kk][3]);
        }

        // ---- O += P V (3 passes fused per B load) ----
        #pragma unroll
        for (int kk = 0; kk < 4; kk++) {
            #pragma unroll
            for (int nt = 0; nt < 16; nt++) {
                uint32_t vh0, vh1, vl0, vl1;
                LDSM2(vh0, vh1, bVH + nt * 1152 + kk * 32);
                LDSM2(vl0, vl1, bVL + nt * 1152 + kk * 32);
                MMA16816(o[nt], ph[kk][0], ph[kk][1], ph[kk][2], ph[kk][3], vh0, vh1);
                MMA16816(o[nt], ph[kk][0], ph[kk][1], ph[kk][2], ph[kk][3], vl0, vl1);
                MMA16816(o[nt], pl[kk][0], pl[kk][1], pl[kk][2], pl[kk][3], vh0, vh1);
            }
        }
    }

    // ---- epilogue: quad-reduce lsum, normalize, store ----
    ls0 += __shfl_xor_sync(0xffffffffu, ls0, 1);
    ls0 += __shfl_xor_sync(0xffffffffu, ls0, 2);
    ls1 += __shfl_xor_sync(0xffffffffu, ls1, 1);
    ls1 += __shfl_xor_sync(0xffffffffu, ls1, 2);
    const float inv0 = 1.0f / ls0, inv1 = 1.0f / ls1;
    float* op = out + ((size_t)b * SEQ + qbase + m0) * DIM;
    #pragma unroll
    for (int nt = 0; nt < 16; nt++) {
        *(float2*)(op + (size_t)g * DIM + nt * 8 + q2) =
            make_float2(o[nt][0] * inv0, o[nt][1] * inv0);
        *(float2*)(op + (size_t)(g + 8) * DIM + nt * 8 + q2) =
            make_float2(o[nt][2] * inv1, o[nt][3] * inv1);
    }
}

// ---------------------------------------------------------------------------
extern "C" void kernel_launch(void* const* d_in, const int* in_sizes, int n_in,
                              void* d_out, int out_size) {
    const float* x  = (const float*)d_in[0];
    const float* Wk = (const float*)d_in[1];
    const float* Wq = (const float*)d_in[2];
    const float* Wv = (const float*)d_in[3];
    float* out = (float*)d_out;

    const size_t qkv_smem = (size_t)(DIM * DIM + QBM * DIM) * sizeof(float);  // 98304

    cudaFuncSetAttribute(qkv_kernel,  cudaFuncAttributeMaxDynamicSharedMemorySize, (int)qkv_smem);
    cudaFuncSetAttribute(attn_kernel, cudaFuncAttributeMaxDynamicSharedMemorySize, SMEM_ATTN);

    dim3 qkv_grid(SEQ / QBM, BATCH, 3);
    qkv_kernel<<<qkv_grid, 256, qkv_smem>>>(x, Wk, Wq, Wv);

    attn_kernel<<<NQT * BATCH, 128, SMEM_ATTN>>>(out);
}